// round 1
// baseline (speedup 1.0000x reference)
#include <cuda_runtime.h>

// DiagonalSISOCell: V=100000, D=64, N=16
// out[v,d,q] = sum_n ( exp(delta_v * A[d,n]) * state[v,d,n] + delta_v*B[d,n]*x[v,d] ) * C[d,n,q]
// delta_v = softplus(x[v,:] @ w_delta + b_delta)

#define V_TOK 100000
#define D_DIM 64

// Scratch for per-token delta (no cudaMalloc allowed).
__device__ float g_delta[V_TOK];

// ---------------------------------------------------------------------------
// Kernel 1: delta[v] = softplus(dot(x[v,:], w) + b). One warp per token row.
// ---------------------------------------------------------------------------
__global__ void delta_kernel(const float* __restrict__ x,
                             const float* __restrict__ w,
                             const float* __restrict__ b)
{
    int warp = (blockIdx.x * blockDim.x + threadIdx.x) >> 5;
    int lane = threadIdx.x & 31;
    if (warp >= V_TOK) return;

    const float* xr = x + warp * D_DIM;
    float s = xr[lane] * w[lane] + xr[lane + 32] * w[lane + 32];
#pragma unroll
    for (int o = 16; o > 0; o >>= 1)
        s += __shfl_xor_sync(0xffffffffu, s, o);

    if (lane == 0) {
        float t = s + b[0];
        // numerically stable softplus, matching jax.nn.softplus
        float sp = fmaxf(t, 0.0f) + log1pf(expf(-fabsf(t)));
        g_delta[warp] = sp;
    }
}

// ---------------------------------------------------------------------------
// Kernel 2: main streaming kernel.
// Warp layout: each warp owns a fixed pair of features (d0, d0+1) and loops
// over tokens v. Lane = (d_sub = lane>>4, q = lane&15). Lane q computes
// new_state for n==q (exactly one exp per element, no redundancy), then the
// 16x16 contraction with C runs via xor-butterfly shuffles against a
// register-resident, xor-permuted C column:
//     C_ord[k] = C[d][q^k][q]   (compile-time register index k)
//     out[q]   = sum_k shfl_xor(new, k) * C_ord[k]
// State load / out store are addr = v*1024 + dpair*32 + lane -> fully
// coalesced 128B per warp.
// ---------------------------------------------------------------------------
__global__ void __launch_bounds__(256, 5)
siso_kernel(const float* __restrict__ x,
            const float* __restrict__ state,
            const float* __restrict__ log_nA,
            const float* __restrict__ Bm,
            const float* __restrict__ Cm,
            float* __restrict__ out,
            int total_warps)
{
    const int gw    = (blockIdx.x * blockDim.x + threadIdx.x) >> 5;
    const int lane  = threadIdx.x & 31;
    const int dpair = gw & 31;           // 32 d-pairs cover D=64
    const int v0    = gw >> 5;
    const int vstr  = total_warps >> 5;

    const int dsub = lane >> 4;
    const int q    = lane & 15;
    const int d    = dpair * 2 + dsub;

    // Per-warp constants (amortized over ~540/vstr token iterations)
    const float A_ln = -__expf(log_nA[d * 16 + q]);   // A[d,n=q]
    const float B_ln = Bm[d * 16 + q];                // B[d,n=q]

    float C_ord[16];
#pragma unroll
    for (int k = 0; k < 16; k++)
        C_ord[k] = Cm[d * 256 + ((q ^ k) << 4) + q];  // C[d][q^k][q]

    const int row_off = dpair * 32 + lane;            // == d*16 + q

    for (int v = v0; v < V_TOK; v += vstr) {
        const float delta = __ldg(&g_delta[v]);
        const float xv    = __ldg(&x[v * 64 + d]);
        const float s     = state[v * 1024 + row_off];

        const float az = __expf(delta * A_ln);
        const float nv = fmaf(az, s, delta * B_ln * xv);

        float acc = nv * C_ord[0];
#pragma unroll
        for (int k = 1; k < 16; k++) {
            float other = __shfl_xor_sync(0xffffffffu, nv, k, 32);
            acc = fmaf(other, C_ord[k], acc);
        }

        out[v * 1024 + row_off] = acc;
    }
}

// ---------------------------------------------------------------------------
// Launch
// ---------------------------------------------------------------------------
extern "C" void kernel_launch(void* const* d_in, const int* in_sizes, int n_in,
                              void* d_out, int out_size)
{
    const float* x       = (const float*)d_in[0];  // [V, D]
    const float* state   = (const float*)d_in[1];  // [V, D, N]
    const float* log_nA  = (const float*)d_in[2];  // [D, N]
    const float* B       = (const float*)d_in[3];  // [D, N]
    const float* C       = (const float*)d_in[4];  // [D, N, N]
    const float* w_delta = (const float*)d_in[5];  // [1, D]
    const float* b_delta = (const float*)d_in[6];  // [1]
    float* out = (float*)d_out;                    // [V, D, N]

    // Kernel 1: 8 warps/block, one warp per token.
    {
        int warps_needed = V_TOK;                 // 100000
        int blocks = (warps_needed + 7) / 8;      // 12500
        delta_kernel<<<blocks, 256>>>(x, w_delta, b_delta);
    }

    // Kernel 2: 740 blocks (5/SM target) * 8 warps = 5920 warps = 185 per d-pair.
    {
        const int blocks = 740;                   // multiple of 4 -> warps % 32 == 0
        const int total_warps = blocks * 8;       // 5920
        siso_kernel<<<blocks, 256>>>(x, state, log_nA, B, C, out, total_warps);
    }
}

// round 2
// speedup vs baseline: 1.6648x; 1.6648x over previous
#include <cuda_runtime.h>

// DiagonalSISOCell: V=100000, D=64, N=16
// out[v,d,q] = sum_n ( exp(delta_v * A[d,n]) * state[v,d,n] + delta_v*B[d,n]*x[v,d] ) * C[d,n,q]
// delta_v = softplus(x[v,:] @ w_delta + b_delta)

#define V_TOK 100000
#define LOG2E 1.4426950408889634f

// Scratch for per-token delta (no cudaMalloc allowed).
__device__ float g_delta[V_TOK];

// ---------------------------------------------------------------------------
// Packed fp32x2 FMA (Blackwell FFMA2 — only reachable via PTX fma.rn.f32x2)
// ---------------------------------------------------------------------------
__device__ __forceinline__ float2 ffma2(float2 a, float2 b, float2 c) {
    float2 r;
    asm("fma.rn.f32x2 %0, %1, %2, %3;"
        : "=l"(*reinterpret_cast<unsigned long long*>(&r))
        : "l"(*reinterpret_cast<unsigned long long*>(&a)),
          "l"(*reinterpret_cast<unsigned long long*>(&b)),
          "l"(*reinterpret_cast<unsigned long long*>(&c)));
    return r;
}

__device__ __forceinline__ float ex2_approx(float x) {
    float r;
    asm("ex2.approx.f32 %0, %1;" : "=f"(r) : "f"(x));
    return r;
}

// ---------------------------------------------------------------------------
// Kernel 1: delta[v] = softplus(dot(x[v,:], w) + b). One warp per token row.
// ---------------------------------------------------------------------------
__global__ void delta_kernel(const float* __restrict__ x,
                             const float* __restrict__ w,
                             const float* __restrict__ b)
{
    int warp = (blockIdx.x * blockDim.x + threadIdx.x) >> 5;
    int lane = threadIdx.x & 31;
    if (warp >= V_TOK) return;

    const float* xr = x + warp * 64;
    float s = xr[lane] * w[lane] + xr[lane + 32] * w[lane + 32];
#pragma unroll
    for (int o = 16; o > 0; o >>= 1)
        s += __shfl_xor_sync(0xffffffffu, s, o);

    if (lane == 0) {
        float t = s + b[0];
        float sp = fmaxf(t, 0.0f) + log1pf(expf(-fabsf(t)));
        g_delta[warp] = sp;
    }
}

// ---------------------------------------------------------------------------
// Kernel 2: shuffle-free main kernel.
//
// Block = 256 thr = 8 warps. Warp w handles feature d = 8*(blockIdx&7) + w.
// Each warp iterates over 64-token tiles of its token chunk:
//   1. coalesced LDG of state[v0..v0+63, d, 0:16]  (8x LDG.128)
//   2. STS into a pitch-20 smem tile (conflict-free transpose)
//   3. each lane owns tokens {l, l+32}: reads its 16 state values via LDS.128,
//      computes new_state with ONE exp per element, contracts with C
//      (broadcast LDS.128 from smem) using packed FFMA2 over (q,q+1) pairs
//   4. STS accumulators back into the tile, coalesced LDS + STG out.
// No shuffles anywhere in the hot loop.
// ---------------------------------------------------------------------------
__global__ void __launch_bounds__(256, 2)
siso_kernel(const float* __restrict__ x,
            const float* __restrict__ state,
            const float* __restrict__ log_nA,
            const float* __restrict__ Bm,
            const float* __restrict__ Cm,
            float* __restrict__ out,
            int chunk_sz)
{
    extern __shared__ float sm[];
    // layout (floats): C_s[8][16][16] @0 (2048) | AB_s[8][16] float2 @2048 (256) |
    //                  tiles[8][64][20] @2304 (10240)
    float*  C_s      = sm;
    float2* AB_s     = reinterpret_cast<float2*>(sm + 2048);
    float*  tile_all = sm + 2304;

    const int tid   = threadIdx.x;
    const int w     = tid >> 5;
    const int l     = tid & 31;
    const int grp   = blockIdx.x & 7;      // d-group (8 d's per block)
    const int chunk = blockIdx.x >> 3;
    const int d     = grp * 8 + w;

    // --- block init: C slice + precomputed (A*log2e, B) pairs ---
    {
        const float* src = Cm + grp * 8 * 256;
        for (int i = tid; i < 2048; i += 256) C_s[i] = src[i];
        if (tid < 128) {
            int dl = tid >> 4, n = tid & 15;
            int gd = grp * 8 + dl;
            float A2 = -__expf(log_nA[gd * 16 + n]) * LOG2E;
            AB_s[tid] = make_float2(A2, Bm[gd * 16 + n]);
        }
    }
    __syncthreads();

    float*        tile = tile_all + w * (64 * 20);
    const float2* AB   = AB_s + w * 16;
    const float*  Cw   = C_s + w * 256;

    const int v_start = chunk * chunk_sz;
    const int v_end   = min(V_TOK, v_start + chunk_sz);

    const int lt = l >> 2;   // loader token sub-index (0..7)
    const int lg = l & 3;    // loader 16B group (0..3)

    for (int v0 = v_start; v0 < v_end; v0 += 64) {
        int nt = v_end - v0; if (nt > 64) nt = 64;

        // 1. coalesced state load (8 tokens x 64B per LDG.128 instr)
        float4 R[8];
        const float4* sp = reinterpret_cast<const float4*>(state) + v0 * 256 + d * 4 + lg;
#pragma unroll
        for (int i = 0; i < 8; i++) {
            int t = lt + 8 * i;
            R[i] = (t < nt) ? sp[t * 256] : make_float4(0.f, 0.f, 0.f, 0.f);
        }
        __syncwarp();   // previous iteration's out-readers are done with the tile
#pragma unroll
        for (int i = 0; i < 8; i++) {
            int t = lt + 8 * i;
            *reinterpret_cast<float4*>(tile + t * 20 + lg * 4) = R[i];
        }
        __syncwarp();

        // 2. per-lane token scalars (tokens A = l, B = l+32)
        const bool va = (l < nt);
        const bool vb = (l + 32 < nt);
        float delta_a = va ? g_delta[v0 + l]      : 0.f;
        float delta_b = vb ? g_delta[v0 + 32 + l] : 0.f;
        float x_a = va ? x[(v0 + l) * 64 + d]      : 0.f;
        float x_b = vb ? x[(v0 + 32 + l) * 64 + d] : 0.f;
        float dx_a = delta_a * x_a;
        float dx_b = delta_b * x_b;

        float2 acc_a[8], acc_b[8];
#pragma unroll
        for (int p = 0; p < 8; p++) {
            acc_a[p] = make_float2(0.f, 0.f);
            acc_b[p] = make_float2(0.f, 0.f);
        }

        // 3. recurrence + contraction (fully unrolled, one exp per element)
        float4 s4a, s4b;
#pragma unroll
        for (int n = 0; n < 16; n++) {
            if ((n & 3) == 0) {
                s4a = *reinterpret_cast<const float4*>(tile + l * 20 + n);
                s4b = *reinterpret_cast<const float4*>(tile + (l + 32) * 20 + n);
            }
            float s_a = (n & 3) == 0 ? s4a.x : (n & 3) == 1 ? s4a.y : (n & 3) == 2 ? s4a.z : s4a.w;
            float s_b = (n & 3) == 0 ? s4b.x : (n & 3) == 1 ? s4b.y : (n & 3) == 2 ? s4b.z : s4b.w;

            float2 ab = AB[n];
            float e_a = ex2_approx(delta_a * ab.x);
            float e_b = ex2_approx(delta_b * ab.x);
            float nv_a = fmaf(e_a, s_a, dx_a * ab.y);
            float nv_b = fmaf(e_b, s_b, dx_b * ab.y);
            float2 nvda = make_float2(nv_a, nv_a);
            float2 nvdb = make_float2(nv_b, nv_b);

            const float4* crow = reinterpret_cast<const float4*>(Cw + n * 16);
#pragma unroll
            for (int p4 = 0; p4 < 4; p4++) {
                float4 c4 = crow[p4];                       // broadcast LDS.128
                float2 c01 = make_float2(c4.x, c4.y);
                float2 c23 = make_float2(c4.z, c4.w);
                acc_a[2 * p4]     = ffma2(nvda, c01, acc_a[2 * p4]);
                acc_a[2 * p4 + 1] = ffma2(nvda, c23, acc_a[2 * p4 + 1]);
                acc_b[2 * p4]     = ffma2(nvdb, c01, acc_b[2 * p4]);
                acc_b[2 * p4 + 1] = ffma2(nvdb, c23, acc_b[2 * p4 + 1]);
            }
        }

        // 4. transpose out through the tile, then coalesced store
        __syncwarp();
#pragma unroll
        for (int p4 = 0; p4 < 4; p4++) {
            *reinterpret_cast<float4*>(tile + l * 20 + 4 * p4) =
                make_float4(acc_a[2 * p4].x, acc_a[2 * p4].y,
                            acc_a[2 * p4 + 1].x, acc_a[2 * p4 + 1].y);
            *reinterpret_cast<float4*>(tile + (l + 32) * 20 + 4 * p4) =
                make_float4(acc_b[2 * p4].x, acc_b[2 * p4].y,
                            acc_b[2 * p4 + 1].x, acc_b[2 * p4 + 1].y);
        }
        __syncwarp();

        float4* op = reinterpret_cast<float4*>(out) + v0 * 256 + d * 4 + lg;
#pragma unroll
        for (int i = 0; i < 8; i++) {
            int t = lt + 8 * i;
            float4 vo = *reinterpret_cast<const float4*>(tile + t * 20 + lg * 4);
            if (t < nt) op[t * 256] = vo;
        }
    }
}

// ---------------------------------------------------------------------------
// Launch
// ---------------------------------------------------------------------------
extern "C" void kernel_launch(void* const* d_in, const int* in_sizes, int n_in,
                              void* d_out, int out_size)
{
    const float* x       = (const float*)d_in[0];  // [V, D]
    const float* state   = (const float*)d_in[1];  // [V, D, N]
    const float* log_nA  = (const float*)d_in[2];  // [D, N]
    const float* B       = (const float*)d_in[3];  // [D, N]
    const float* C       = (const float*)d_in[4];  // [D, N, N]
    const float* w_delta = (const float*)d_in[5];  // [1, D]
    const float* b_delta = (const float*)d_in[6];  // [1]
    float* out = (float*)d_out;                    // [V, D, N]

    // Kernel 1: one warp per token.
    delta_kernel<<<(V_TOK + 7) / 8, 256>>>(x, w_delta, b_delta);

    // Kernel 2: 8 d-groups x 37 chunks = 296 blocks = 2/SM, 1 wave.
    const int n_chunks = 37;
    const int chunk_sz = (V_TOK + n_chunks - 1) / n_chunks;   // 2703
    const int smem_bytes = (2048 + 256 + 8 * 64 * 20) * 4;    // 50176 B

    cudaFuncSetAttribute(siso_kernel,
                         cudaFuncAttributeMaxDynamicSharedMemorySize, smem_bytes);
    siso_kernel<<<8 * n_chunks, 256, smem_bytes>>>(x, state, log_nA, B, C, out, chunk_sz);
}